// round 4
// baseline (speedup 1.0000x reference)
#include <cuda_runtime.h>
#include <cstddef>

// ---------------------------------------------------------------------------
// MultiHeadAttention forward, fp32 baseline.
//   B=2, S=2048, D=1024, H=16, Dh=64
//   q = x@Wq^T, k = x@Wk^T, v = x@Wv^T          (kept in [B*S, H*Dh] layout)
//   scores[b,h] = q_bh @ k_bh^T   (NO 1/sqrt(d) scaling, per reference)
//   P = softmax(scores, axis=-1)
//   attn = P @ v_bh  -> [B*S, H*Dh]
//   out = attn @ Wp^T + bp
// ---------------------------------------------------------------------------

#define BATCH   2
#define SEQ     2048
#define DMODEL  1024
#define HEADS   16
#define DHEAD   64
#define MROWS   (BATCH * SEQ)          // 4096
#define BH      (BATCH * HEADS)        // 32

// Scratch (static device globals: allocation-guard safe)
__device__ float g_q   [MROWS * DMODEL];
__device__ float g_k   [MROWS * DMODEL];
__device__ float g_v   [MROWS * DMODEL];
__device__ float g_attn[MROWS * DMODEL];
__device__ float g_sc  [(size_t)BH * SEQ * SEQ];   // 512 MB

#define TS 64          // output tile (TS x TS)
#define KT 16          // k-tile

// ---------------------------------------------------------------------------
// NT GEMM: C[M,N] = A[M,K] @ B[N,K]^T (+bias). A,B,C row-major, ld = K,K,N.
// M,N multiples of 64; K multiple of 16. 256 threads, 4x4 microtile.
// ---------------------------------------------------------------------------
__global__ void gemm_nt_kernel(const float* __restrict__ A,
                               const float* __restrict__ B,
                               float* __restrict__ C,
                               const float* __restrict__ bias,
                               int M, int N, int K)
{
    __shared__ float As[KT][TS + 1];
    __shared__ float Bs[KT][TS + 1];

    const int tid = threadIdx.x;
    const int tx  = tid & 15;
    const int ty  = tid >> 4;
    const int m0  = blockIdx.y * TS;
    const int n0  = blockIdx.x * TS;

    const int lm = tid >> 2;          // 0..63
    const int lk = (tid & 3) * 4;     // 0,4,8,12

    float c[4][4] = {};

    for (int k0 = 0; k0 < K; k0 += KT) {
        float4 a4 = *reinterpret_cast<const float4*>(&A[(size_t)(m0 + lm) * K + k0 + lk]);
        float4 b4 = *reinterpret_cast<const float4*>(&B[(size_t)(n0 + lm) * K + k0 + lk]);
        As[lk + 0][lm] = a4.x; As[lk + 1][lm] = a4.y;
        As[lk + 2][lm] = a4.z; As[lk + 3][lm] = a4.w;
        Bs[lk + 0][lm] = b4.x; Bs[lk + 1][lm] = b4.y;
        Bs[lk + 2][lm] = b4.z; Bs[lk + 3][lm] = b4.w;
        __syncthreads();

        #pragma unroll
        for (int kk = 0; kk < KT; kk++) {
            float a[4], b[4];
            #pragma unroll
            for (int i = 0; i < 4; i++) { a[i] = As[kk][ty + i * 16]; }
            #pragma unroll
            for (int j = 0; j < 4; j++) { b[j] = Bs[kk][tx + j * 16]; }
            #pragma unroll
            for (int i = 0; i < 4; i++)
                #pragma unroll
                for (int j = 0; j < 4; j++)
                    c[i][j] = fmaf(a[i], b[j], c[i][j]);
        }
        __syncthreads();
    }

    #pragma unroll
    for (int i = 0; i < 4; i++) {
        const int m = m0 + ty + i * 16;
        #pragma unroll
        for (int j = 0; j < 4; j++) {
            const int n = n0 + tx + j * 16;
            float r = c[i][j];
            if (bias) r += bias[n];
            C[(size_t)m * N + n] = r;
        }
    }
}

// ---------------------------------------------------------------------------
// scores[b,h] (SEQ x SEQ) = q_bh (SEQ x 64) @ k_bh^T, lda = ldb = DMODEL.
// grid (SEQ/64, SEQ/64, BH)
// ---------------------------------------------------------------------------
__global__ void scores_kernel()
{
    __shared__ float As[KT][TS + 1];
    __shared__ float Bs[KT][TS + 1];

    const int bh = blockIdx.z;
    const int b  = bh >> 4;
    const int h  = bh & 15;
    const float* A = g_q + (size_t)b * SEQ * DMODEL + h * DHEAD;
    const float* B = g_k + (size_t)b * SEQ * DMODEL + h * DHEAD;
    float*       C = g_sc + (size_t)bh * SEQ * SEQ;

    const int tid = threadIdx.x;
    const int tx  = tid & 15;
    const int ty  = tid >> 4;
    const int m0  = blockIdx.y * TS;
    const int n0  = blockIdx.x * TS;
    const int lm  = tid >> 2;
    const int lk  = (tid & 3) * 4;

    float c[4][4] = {};

    for (int k0 = 0; k0 < DHEAD; k0 += KT) {
        float4 a4 = *reinterpret_cast<const float4*>(&A[(size_t)(m0 + lm) * DMODEL + k0 + lk]);
        float4 b4 = *reinterpret_cast<const float4*>(&B[(size_t)(n0 + lm) * DMODEL + k0 + lk]);
        As[lk + 0][lm] = a4.x; As[lk + 1][lm] = a4.y;
        As[lk + 2][lm] = a4.z; As[lk + 3][lm] = a4.w;
        Bs[lk + 0][lm] = b4.x; Bs[lk + 1][lm] = b4.y;
        Bs[lk + 2][lm] = b4.z; Bs[lk + 3][lm] = b4.w;
        __syncthreads();

        #pragma unroll
        for (int kk = 0; kk < KT; kk++) {
            float a[4], bb[4];
            #pragma unroll
            for (int i = 0; i < 4; i++) { a[i]  = As[kk][ty + i * 16]; }
            #pragma unroll
            for (int j = 0; j < 4; j++) { bb[j] = Bs[kk][tx + j * 16]; }
            #pragma unroll
            for (int i = 0; i < 4; i++)
                #pragma unroll
                for (int j = 0; j < 4; j++)
                    c[i][j] = fmaf(a[i], bb[j], c[i][j]);
        }
        __syncthreads();
    }

    #pragma unroll
    for (int i = 0; i < 4; i++)
        #pragma unroll
        for (int j = 0; j < 4; j++)
            C[(size_t)(m0 + ty + i * 16) * SEQ + (n0 + tx + j * 16)] = c[i][j];
}

// ---------------------------------------------------------------------------
// Row softmax over SEQ=2048 columns. One 256-thread block per row.
// ---------------------------------------------------------------------------
__global__ void softmax_kernel()
{
    __shared__ float red[256];
    const int tid = threadIdx.x;
    float* p = g_sc + (size_t)blockIdx.x * SEQ;

    float v[8];
    float mx = -1e30f;
    #pragma unroll
    for (int i = 0; i < 8; i++) {
        v[i] = p[tid + i * 256];
        mx = fmaxf(mx, v[i]);
    }
    red[tid] = mx;
    __syncthreads();
    for (int s = 128; s > 0; s >>= 1) {
        if (tid < s) red[tid] = fmaxf(red[tid], red[tid + s]);
        __syncthreads();
    }
    mx = red[0];
    __syncthreads();

    float sum = 0.f;
    #pragma unroll
    for (int i = 0; i < 8; i++) {
        v[i] = __expf(v[i] - mx);
        sum += v[i];
    }
    red[tid] = sum;
    __syncthreads();
    for (int s = 128; s > 0; s >>= 1) {
        if (tid < s) red[tid] += red[tid + s];
        __syncthreads();
    }
    const float inv = 1.0f / red[0];
    #pragma unroll
    for (int i = 0; i < 8; i++)
        p[tid + i * 256] = v[i] * inv;
}

// ---------------------------------------------------------------------------
// attn_bh (SEQ x 64) = P_bh (SEQ x SEQ) @ v_bh (SEQ x 64).  NN GEMM.
// grid (1, SEQ/64, BH). Output into g_attn at [row, h*64+d], ldc = DMODEL.
// ---------------------------------------------------------------------------
__global__ void pv_kernel()
{
    __shared__ float As[KT][TS + 1];
    __shared__ float Bs[KT][TS + 1];

    const int bh = blockIdx.z;
    const int b  = bh >> 4;
    const int h  = bh & 15;
    const float* A = g_sc   + (size_t)bh * SEQ * SEQ;                 // lda = SEQ
    const float* B = g_v    + (size_t)b * SEQ * DMODEL + h * DHEAD;   // ldb = DMODEL
    float*       C = g_attn + (size_t)b * SEQ * DMODEL + h * DHEAD;   // ldc = DMODEL

    const int tid = threadIdx.x;
    const int tx  = tid & 15;
    const int ty  = tid >> 4;
    const int m0  = blockIdx.y * TS;

    const int lm  = tid >> 2;          // A-load row 0..63
    const int lk  = (tid & 3) * 4;     // A-load k 0,4,8,12
    const int bk  = (tid >> 6) * 4;    // B-load k base 0,4,8,12
    const int bn  = tid & 63;          // B-load col 0..63

    float c[4][4] = {};

    for (int k0 = 0; k0 < SEQ; k0 += KT) {
        float4 a4 = *reinterpret_cast<const float4*>(&A[(size_t)(m0 + lm) * SEQ + k0 + lk]);
        As[lk + 0][lm] = a4.x; As[lk + 1][lm] = a4.y;
        As[lk + 2][lm] = a4.z; As[lk + 3][lm] = a4.w;
        #pragma unroll
        for (int r = 0; r < 4; r++)
            Bs[bk + r][bn] = B[(size_t)(k0 + bk + r) * DMODEL + bn];
        __syncthreads();

        #pragma unroll
        for (int kk = 0; kk < KT; kk++) {
            float a[4], bb[4];
            #pragma unroll
            for (int i = 0; i < 4; i++) { a[i]  = As[kk][ty + i * 16]; }
            #pragma unroll
            for (int j = 0; j < 4; j++) { bb[j] = Bs[kk][tx + j * 16]; }
            #pragma unroll
            for (int i = 0; i < 4; i++)
                #pragma unroll
                for (int j = 0; j < 4; j++)
                    c[i][j] = fmaf(a[i], bb[j], c[i][j]);
        }
        __syncthreads();
    }

    #pragma unroll
    for (int i = 0; i < 4; i++)
        #pragma unroll
        for (int j = 0; j < 4; j++)
            C[(size_t)(m0 + ty + i * 16) * DMODEL + (tx + j * 16)] = c[i][j];
}

// ---------------------------------------------------------------------------
extern "C" void kernel_launch(void* const* d_in, const int* in_sizes, int n_in,
                              void* d_out, int out_size)
{
    const float* x  = (const float*)d_in[0];
    // d_in[1] = attn_weights (unused by reference forward)
    const float* Wq = (const float*)d_in[2];
    const float* Wk = (const float*)d_in[3];
    const float* Wv = (const float*)d_in[4];
    const float* Wp = (const float*)d_in[5];
    const float* bp = (const float*)d_in[6];
    float* out = (float*)d_out;

    float *q, *k, *v, *attn;
    cudaGetSymbolAddress((void**)&q,    g_q);
    cudaGetSymbolAddress((void**)&k,    g_k);
    cudaGetSymbolAddress((void**)&v,    g_v);
    cudaGetSymbolAddress((void**)&attn, g_attn);

    const dim3 blk(256);
    const dim3 grid_proj(DMODEL / TS, MROWS / TS);   // (16, 64)

    // QKV projections
    gemm_nt_kernel<<<grid_proj, blk>>>(x, Wq, q, nullptr, MROWS, DMODEL, DMODEL);
    gemm_nt_kernel<<<grid_proj, blk>>>(x, Wk, k, nullptr, MROWS, DMODEL, DMODEL);
    gemm_nt_kernel<<<grid_proj, blk>>>(x, Wv, v, nullptr, MROWS, DMODEL, DMODEL);

    // Attention
    scores_kernel <<<dim3(SEQ / TS, SEQ / TS, BH), blk>>>();
    softmax_kernel<<<BH * SEQ, blk>>>();
    pv_kernel     <<<dim3(1, SEQ / TS, BH), blk>>>();

    // Output projection (+bias)
    gemm_nt_kernel<<<grid_proj, blk>>>(attn, Wp, out, bp, MROWS, DMODEL, DMODEL);
}

// round 5
// speedup vs baseline: 1.5535x; 1.5535x over previous
#include <cuda_runtime.h>
#include <cstddef>

// ---------------------------------------------------------------------------
// MultiHeadAttention forward, fp32, round 4: 128x128 / 8x8-microtile GEMMs,
// double-buffered smem, float4 LDS. Targets the L1-bound profile seen in R3
// (fma=36%, L1=94.5%): raise FFMA per LDS by ~6x.
//   B=2, S=2048, D=1024, H=16, Dh=64
// ---------------------------------------------------------------------------

#define BATCH   2
#define SEQ     2048
#define DMODEL  1024
#define HEADS   16
#define DHEAD   64
#define MROWS   (BATCH * SEQ)          // 4096
#define BH      (BATCH * HEADS)        // 32
#define KT      16                     // k-stage depth

// Scratch (static device globals: allocation-guard safe)
__device__ float g_q   [MROWS * DMODEL];
__device__ float g_k   [MROWS * DMODEL];
__device__ float g_v   [MROWS * DMODEL];
__device__ float g_attn[MROWS * DMODEL];
__device__ float g_sc  [(size_t)BH * SEQ * SEQ];   // 512 MB

// ---------------------------------------------------------------------------
// 128x128 NT GEMM body. C[M,N] = A[M,K] @ B[N,K]^T (+bias).
// 256 threads, 8x8 microtile, double-buffered KT=16 stages.
// Row stride 132 floats keeps 16B alignment for float4 LDS (132*4 % 16 == 0).
// ---------------------------------------------------------------------------
struct Smem128 {
    float As[2][KT][132];
    float Bs[2][KT][132];
};

__device__ __forceinline__ void gemm128_body(
    const float* __restrict__ A, int lda,
    const float* __restrict__ B, int ldb,
    float*       __restrict__ C, int ldc,
    int K, const float* __restrict__ bias,
    int m0, int n0, Smem128& s)
{
    const int tid = threadIdx.x;
    const int tx  = tid & 15;          // n micro group
    const int ty  = tid >> 4;          // m micro group
    const int lr  = tid >> 2;          // load row 0..63
    const int lk4 = (tid & 3) * 4;     // load k 0,4,8,12

    float acc[8][8] = {};

    // prologue: stage 0 -> smem buf 0
    {
        float4 a0 = *(const float4*)&A[(size_t)(m0 + lr)      * lda + lk4];
        float4 a1 = *(const float4*)&A[(size_t)(m0 + 64 + lr) * lda + lk4];
        float4 b0 = *(const float4*)&B[(size_t)(n0 + lr)      * ldb + lk4];
        float4 b1 = *(const float4*)&B[(size_t)(n0 + 64 + lr) * ldb + lk4];
        s.As[0][lk4+0][lr]    = a0.x; s.As[0][lk4+1][lr]    = a0.y;
        s.As[0][lk4+2][lr]    = a0.z; s.As[0][lk4+3][lr]    = a0.w;
        s.As[0][lk4+0][64+lr] = a1.x; s.As[0][lk4+1][64+lr] = a1.y;
        s.As[0][lk4+2][64+lr] = a1.z; s.As[0][lk4+3][64+lr] = a1.w;
        s.Bs[0][lk4+0][lr]    = b0.x; s.Bs[0][lk4+1][lr]    = b0.y;
        s.Bs[0][lk4+2][lr]    = b0.z; s.Bs[0][lk4+3][lr]    = b0.w;
        s.Bs[0][lk4+0][64+lr] = b1.x; s.Bs[0][lk4+1][64+lr] = b1.y;
        s.Bs[0][lk4+2][64+lr] = b1.z; s.Bs[0][lk4+3][64+lr] = b1.w;
    }
    __syncthreads();

    int buf = 0;
    for (int k0 = KT; k0 <= K; k0 += KT) {
        const bool has_next = (k0 < K);
        float4 a0n, a1n, b0n, b1n;
        if (has_next) {
            a0n = *(const float4*)&A[(size_t)(m0 + lr)      * lda + k0 + lk4];
            a1n = *(const float4*)&A[(size_t)(m0 + 64 + lr) * lda + k0 + lk4];
            b0n = *(const float4*)&B[(size_t)(n0 + lr)      * ldb + k0 + lk4];
            b1n = *(const float4*)&B[(size_t)(n0 + 64 + lr) * ldb + k0 + lk4];
        }

        #pragma unroll
        for (int kk = 0; kk < KT; kk++) {
            float4 av0 = *(const float4*)&s.As[buf][kk][ty * 4];
            float4 av1 = *(const float4*)&s.As[buf][kk][64 + ty * 4];
            float4 bv0 = *(const float4*)&s.Bs[buf][kk][tx * 4];
            float4 bv1 = *(const float4*)&s.Bs[buf][kk][64 + tx * 4];
            const float a[8] = {av0.x, av0.y, av0.z, av0.w, av1.x, av1.y, av1.z, av1.w};
            const float b[8] = {bv0.x, bv0.y, bv0.z, bv0.w, bv1.x, bv1.y, bv1.z, bv1.w};
            #pragma unroll
            for (int i = 0; i < 8; i++)
                #pragma unroll
                for (int j = 0; j < 8; j++)
                    acc[i][j] = fmaf(a[i], b[j], acc[i][j]);
        }

        if (has_next) {
            const int nb = buf ^ 1;
            s.As[nb][lk4+0][lr]    = a0n.x; s.As[nb][lk4+1][lr]    = a0n.y;
            s.As[nb][lk4+2][lr]    = a0n.z; s.As[nb][lk4+3][lr]    = a0n.w;
            s.As[nb][lk4+0][64+lr] = a1n.x; s.As[nb][lk4+1][64+lr] = a1n.y;
            s.As[nb][lk4+2][64+lr] = a1n.z; s.As[nb][lk4+3][64+lr] = a1n.w;
            s.Bs[nb][lk4+0][lr]    = b0n.x; s.Bs[nb][lk4+1][lr]    = b0n.y;
            s.Bs[nb][lk4+2][lr]    = b0n.z; s.Bs[nb][lk4+3][lr]    = b0n.w;
            s.Bs[nb][lk4+0][64+lr] = b1n.x; s.Bs[nb][lk4+1][64+lr] = b1n.y;
            s.Bs[nb][lk4+2][64+lr] = b1n.z; s.Bs[nb][lk4+3][64+lr] = b1n.w;
            __syncthreads();
        }
        buf ^= 1;
    }

    // epilogue: 16 float4 stores
    #pragma unroll
    for (int i = 0; i < 8; i++) {
        const int m = m0 + ((i < 4) ? (ty * 4 + i) : (64 + ty * 4 + i - 4));
        const int nA = n0 + tx * 4;
        const int nB = n0 + 64 + tx * 4;
        float4 r0 = make_float4(acc[i][0], acc[i][1], acc[i][2], acc[i][3]);
        float4 r1 = make_float4(acc[i][4], acc[i][5], acc[i][6], acc[i][7]);
        if (bias) {
            r0.x += bias[nA+0]; r0.y += bias[nA+1]; r0.z += bias[nA+2]; r0.w += bias[nA+3];
            r1.x += bias[nB+0]; r1.y += bias[nB+1]; r1.z += bias[nB+2]; r1.w += bias[nB+3];
        }
        *(float4*)&C[(size_t)m * ldc + nA] = r0;
        *(float4*)&C[(size_t)m * ldc + nB] = r1;
    }
}

// ---------------------------------------------------------------------------
// Projection GEMM: C[M,N] = A[M,K] @ W[N,K]^T (+bias). grid (N/128, M/128).
// ---------------------------------------------------------------------------
__global__ void __launch_bounds__(256, 2)
proj_kernel(const float* __restrict__ A,
            const float* __restrict__ W,
            float* __restrict__ C,
            const float* __restrict__ bias,
            int N, int K)
{
    __shared__ Smem128 s;
    gemm128_body(A, K, W, K, C, N, K, bias, blockIdx.y * 128, blockIdx.x * 128, s);
}

// ---------------------------------------------------------------------------
// scores[b,h] = q_bh @ k_bh^T.  grid (SEQ/128, SEQ/128, BH).
// ---------------------------------------------------------------------------
__global__ void __launch_bounds__(256, 2)
scores_kernel()
{
    __shared__ Smem128 s;
    const int bh = blockIdx.z;
    const int b  = bh >> 4;
    const int h  = bh & 15;
    const float* A = g_q + (size_t)b * SEQ * DMODEL + h * DHEAD;
    const float* B = g_k + (size_t)b * SEQ * DMODEL + h * DHEAD;
    float*       C = g_sc + (size_t)bh * SEQ * SEQ;
    gemm128_body(A, DMODEL, B, DMODEL, C, SEQ, DHEAD, nullptr,
                 blockIdx.y * 128, blockIdx.x * 128, s);
}

// ---------------------------------------------------------------------------
// Row softmax over SEQ=2048 columns. One 256-thread block per row, float4 I/O.
// ---------------------------------------------------------------------------
__global__ void __launch_bounds__(256)
softmax_kernel()
{
    __shared__ float red[8];
    const int tid  = threadIdx.x;
    const int lane = tid & 31;
    const int warp = tid >> 5;
    float4* p4 = reinterpret_cast<float4*>(g_sc + (size_t)blockIdx.x * SEQ);

    float4 x0 = p4[tid];
    float4 x1 = p4[tid + 256];

    float mx = fmaxf(fmaxf(fmaxf(x0.x, x0.y), fmaxf(x0.z, x0.w)),
                     fmaxf(fmaxf(x1.x, x1.y), fmaxf(x1.z, x1.w)));
    #pragma unroll
    for (int o = 16; o > 0; o >>= 1)
        mx = fmaxf(mx, __shfl_xor_sync(0xffffffffu, mx, o));
    if (lane == 0) red[warp] = mx;
    __syncthreads();
    if (warp == 0) {
        float m = red[lane & 7];
        #pragma unroll
        for (int o = 4; o > 0; o >>= 1)
            m = fmaxf(m, __shfl_xor_sync(0xffffffffu, m, o));
        if (lane == 0) red[0] = m;
    }
    __syncthreads();
    mx = red[0];
    __syncthreads();

    x0.x = __expf(x0.x - mx); x0.y = __expf(x0.y - mx);
    x0.z = __expf(x0.z - mx); x0.w = __expf(x0.w - mx);
    x1.x = __expf(x1.x - mx); x1.y = __expf(x1.y - mx);
    x1.z = __expf(x1.z - mx); x1.w = __expf(x1.w - mx);
    float sum = x0.x + x0.y + x0.z + x0.w + x1.x + x1.y + x1.z + x1.w;
    #pragma unroll
    for (int o = 16; o > 0; o >>= 1)
        sum += __shfl_xor_sync(0xffffffffu, sum, o);
    if (lane == 0) red[warp] = sum;
    __syncthreads();
    if (warp == 0) {
        float sm = red[lane & 7];
        #pragma unroll
        for (int o = 4; o > 0; o >>= 1)
            sm += __shfl_xor_sync(0xffffffffu, sm, o);
        if (lane == 0) red[0] = sm;
    }
    __syncthreads();
    const float inv = 1.0f / red[0];

    x0.x *= inv; x0.y *= inv; x0.z *= inv; x0.w *= inv;
    x1.x *= inv; x1.y *= inv; x1.z *= inv; x1.w *= inv;
    p4[tid]       = x0;
    p4[tid + 256] = x1;
}

// ---------------------------------------------------------------------------
// attn_bh (SEQ x 64) = P_bh (SEQ x SEQ) @ v_bh (SEQ x 64). NN GEMM.
// Tile 128x64, 256 threads, 8x4 microtile, double-buffered.
// grid (1, SEQ/128, BH).
// ---------------------------------------------------------------------------
__global__ void __launch_bounds__(256, 2)
pv_kernel()
{
    __shared__ float As[2][KT][132];
    __shared__ float Bs[2][KT][68];

    const int bh = blockIdx.z;
    const int b  = bh >> 4;
    const int h  = bh & 15;
    const float* A = g_sc   + (size_t)bh * SEQ * SEQ;                 // lda = SEQ
    const float* B = g_v    + (size_t)b * SEQ * DMODEL + h * DHEAD;   // ldb = DMODEL
    float*       C = g_attn + (size_t)b * SEQ * DMODEL + h * DHEAD;   // ldc = DMODEL

    const int tid = threadIdx.x;
    const int tx  = tid & 15;          // cols tx*4 .. tx*4+3
    const int ty  = tid >> 4;          // rows ty*4, 64+ty*4
    const int lr  = tid >> 2;          // A-load row 0..63
    const int lk4 = (tid & 3) * 4;     // A-load k 0,4,8,12
    const int bk  = tid >> 4;          // B-load k 0..15
    const int bn  = (tid & 15) * 4;    // B-load col

    const int m0 = blockIdx.y * 128;

    float acc[8][4] = {};

    // prologue
    {
        float4 a0 = *(const float4*)&A[(size_t)(m0 + lr)      * SEQ + lk4];
        float4 a1 = *(const float4*)&A[(size_t)(m0 + 64 + lr) * SEQ + lk4];
        float4 bv = *(const float4*)&B[(size_t)bk * DMODEL + bn];
        As[0][lk4+0][lr]    = a0.x; As[0][lk4+1][lr]    = a0.y;
        As[0][lk4+2][lr]    = a0.z; As[0][lk4+3][lr]    = a0.w;
        As[0][lk4+0][64+lr] = a1.x; As[0][lk4+1][64+lr] = a1.y;
        As[0][lk4+2][64+lr] = a1.z; As[0][lk4+3][64+lr] = a1.w;
        *(float4*)&Bs[0][bk][bn] = bv;
    }
    __syncthreads();

    int buf = 0;
    for (int k0 = KT; k0 <= SEQ; k0 += KT) {
        const bool has_next = (k0 < SEQ);
        float4 a0n, a1n, bvn;
        if (has_next) {
            a0n = *(const float4*)&A[(size_t)(m0 + lr)      * SEQ + k0 + lk4];
            a1n = *(const float4*)&A[(size_t)(m0 + 64 + lr) * SEQ + k0 + lk4];
            bvn = *(const float4*)&B[(size_t)(k0 + bk) * DMODEL + bn];
        }

        #pragma unroll
        for (int kk = 0; kk < KT; kk++) {
            float4 av0 = *(const float4*)&As[buf][kk][ty * 4];
            float4 av1 = *(const float4*)&As[buf][kk][64 + ty * 4];
            float4 bv  = *(const float4*)&Bs[buf][kk][tx * 4];
            const float a[8] = {av0.x, av0.y, av0.z, av0.w, av1.x, av1.y, av1.z, av1.w};
            const float bb[4] = {bv.x, bv.y, bv.z, bv.w};
            #pragma unroll
            for (int i = 0; i < 8; i++)
                #pragma unroll
                for (int j = 0; j < 4; j++)
                    acc[i][j] = fmaf(a[i], bb[j], acc[i][j]);
        }

        if (has_next) {
            const int nb = buf ^ 1;
            As[nb][lk4+0][lr]    = a0n.x; As[nb][lk4+1][lr]    = a0n.y;
            As[nb][lk4+2][lr]    = a0n.z; As[nb][lk4+3][lr]    = a0n.w;
            As[nb][lk4+0][64+lr] = a1n.x; As[nb][lk4+1][64+lr] = a1n.y;
            As[nb][lk4+2][64+lr] = a1n.z; As[nb][lk4+3][64+lr] = a1n.w;
            *(float4*)&Bs[nb][bk][bn] = bvn;
            __syncthreads();
        }
        buf ^= 1;
    }

    #pragma unroll
    for (int i = 0; i < 8; i++) {
        const int m = m0 + ((i < 4) ? (ty * 4 + i) : (64 + ty * 4 + i - 4));
        *(float4*)&C[(size_t)m * DMODEL + tx * 4] =
            make_float4(acc[i][0], acc[i][1], acc[i][2], acc[i][3]);
    }
}

// ---------------------------------------------------------------------------
extern "C" void kernel_launch(void* const* d_in, const int* in_sizes, int n_in,
                              void* d_out, int out_size)
{
    const float* x  = (const float*)d_in[0];
    // d_in[1] = attn_weights (unused by reference forward)
    const float* Wq = (const float*)d_in[2];
    const float* Wk = (const float*)d_in[3];
    const float* Wv = (const float*)d_in[4];
    const float* Wp = (const float*)d_in[5];
    const float* bp = (const float*)d_in[6];
    float* out = (float*)d_out;

    float *q, *k, *v, *attn;
    cudaGetSymbolAddress((void**)&q,    g_q);
    cudaGetSymbolAddress((void**)&k,    g_k);
    cudaGetSymbolAddress((void**)&v,    g_v);
    cudaGetSymbolAddress((void**)&attn, g_attn);

    const dim3 blk(256);
    const dim3 grid_proj(DMODEL / 128, MROWS / 128);   // (8, 32)

    // QKV projections
    proj_kernel<<<grid_proj, blk>>>(x, Wq, q, nullptr, DMODEL, DMODEL);
    proj_kernel<<<grid_proj, blk>>>(x, Wk, k, nullptr, DMODEL, DMODEL);
    proj_kernel<<<grid_proj, blk>>>(x, Wv, v, nullptr, DMODEL, DMODEL);

    // Attention
    scores_kernel <<<dim3(SEQ / 128, SEQ / 128, BH), blk>>>();
    softmax_kernel<<<BH * SEQ, blk>>>();
    pv_kernel     <<<dim3(1, SEQ / 128, BH), blk>>>();

    // Output projection (+bias)
    proj_kernel<<<grid_proj, blk>>>(attn, Wp, out, bp, DMODEL, DMODEL);
}

// round 6
// speedup vs baseline: 1.5550x; 1.0010x over previous
#include <cuda_runtime.h>
#include <cstddef>

// ---------------------------------------------------------------------------
// MultiHeadAttention forward, fp32, round 4: 128x128 / 8x8-microtile GEMMs,
// double-buffered smem, float4 LDS. Targets the L1-bound profile seen in R3
// (fma=36%, L1=94.5%): raise FFMA per LDS by ~6x.
//   B=2, S=2048, D=1024, H=16, Dh=64
// ---------------------------------------------------------------------------

#define BATCH   2
#define SEQ     2048
#define DMODEL  1024
#define HEADS   16
#define DHEAD   64
#define MROWS   (BATCH * SEQ)          // 4096
#define BH      (BATCH * HEADS)        // 32
#define KT      16                     // k-stage depth

// Scratch (static device globals: allocation-guard safe)
__device__ float g_q   [MROWS * DMODEL];
__device__ float g_k   [MROWS * DMODEL];
__device__ float g_v   [MROWS * DMODEL];
__device__ float g_attn[MROWS * DMODEL];
__device__ float g_sc  [(size_t)BH * SEQ * SEQ];   // 512 MB

// ---------------------------------------------------------------------------
// 128x128 NT GEMM body. C[M,N] = A[M,K] @ B[N,K]^T (+bias).
// 256 threads, 8x8 microtile, double-buffered KT=16 stages.
// Row stride 132 floats keeps 16B alignment for float4 LDS (132*4 % 16 == 0).
// ---------------------------------------------------------------------------
struct Smem128 {
    float As[2][KT][132];
    float Bs[2][KT][132];
};

__device__ __forceinline__ void gemm128_body(
    const float* __restrict__ A, int lda,
    const float* __restrict__ B, int ldb,
    float*       __restrict__ C, int ldc,
    int K, const float* __restrict__ bias,
    int m0, int n0, Smem128& s)
{
    const int tid = threadIdx.x;
    const int tx  = tid & 15;          // n micro group
    const int ty  = tid >> 4;          // m micro group
    const int lr  = tid >> 2;          // load row 0..63
    const int lk4 = (tid & 3) * 4;     // load k 0,4,8,12

    float acc[8][8] = {};

    // prologue: stage 0 -> smem buf 0
    {
        float4 a0 = *(const float4*)&A[(size_t)(m0 + lr)      * lda + lk4];
        float4 a1 = *(const float4*)&A[(size_t)(m0 + 64 + lr) * lda + lk4];
        float4 b0 = *(const float4*)&B[(size_t)(n0 + lr)      * ldb + lk4];
        float4 b1 = *(const float4*)&B[(size_t)(n0 + 64 + lr) * ldb + lk4];
        s.As[0][lk4+0][lr]    = a0.x; s.As[0][lk4+1][lr]    = a0.y;
        s.As[0][lk4+2][lr]    = a0.z; s.As[0][lk4+3][lr]    = a0.w;
        s.As[0][lk4+0][64+lr] = a1.x; s.As[0][lk4+1][64+lr] = a1.y;
        s.As[0][lk4+2][64+lr] = a1.z; s.As[0][lk4+3][64+lr] = a1.w;
        s.Bs[0][lk4+0][lr]    = b0.x; s.Bs[0][lk4+1][lr]    = b0.y;
        s.Bs[0][lk4+2][lr]    = b0.z; s.Bs[0][lk4+3][lr]    = b0.w;
        s.Bs[0][lk4+0][64+lr] = b1.x; s.Bs[0][lk4+1][64+lr] = b1.y;
        s.Bs[0][lk4+2][64+lr] = b1.z; s.Bs[0][lk4+3][64+lr] = b1.w;
    }
    __syncthreads();

    int buf = 0;
    for (int k0 = KT; k0 <= K; k0 += KT) {
        const bool has_next = (k0 < K);
        float4 a0n, a1n, b0n, b1n;
        if (has_next) {
            a0n = *(const float4*)&A[(size_t)(m0 + lr)      * lda + k0 + lk4];
            a1n = *(const float4*)&A[(size_t)(m0 + 64 + lr) * lda + k0 + lk4];
            b0n = *(const float4*)&B[(size_t)(n0 + lr)      * ldb + k0 + lk4];
            b1n = *(const float4*)&B[(size_t)(n0 + 64 + lr) * ldb + k0 + lk4];
        }

        #pragma unroll
        for (int kk = 0; kk < KT; kk++) {
            float4 av0 = *(const float4*)&s.As[buf][kk][ty * 4];
            float4 av1 = *(const float4*)&s.As[buf][kk][64 + ty * 4];
            float4 bv0 = *(const float4*)&s.Bs[buf][kk][tx * 4];
            float4 bv1 = *(const float4*)&s.Bs[buf][kk][64 + tx * 4];
            const float a[8] = {av0.x, av0.y, av0.z, av0.w, av1.x, av1.y, av1.z, av1.w};
            const float b[8] = {bv0.x, bv0.y, bv0.z, bv0.w, bv1.x, bv1.y, bv1.z, bv1.w};
            #pragma unroll
            for (int i = 0; i < 8; i++)
                #pragma unroll
                for (int j = 0; j < 8; j++)
                    acc[i][j] = fmaf(a[i], b[j], acc[i][j]);
        }

        if (has_next) {
            const int nb = buf ^ 1;
            s.As[nb][lk4+0][lr]    = a0n.x; s.As[nb][lk4+1][lr]    = a0n.y;
            s.As[nb][lk4+2][lr]    = a0n.z; s.As[nb][lk4+3][lr]    = a0n.w;
            s.As[nb][lk4+0][64+lr] = a1n.x; s.As[nb][lk4+1][64+lr] = a1n.y;
            s.As[nb][lk4+2][64+lr] = a1n.z; s.As[nb][lk4+3][64+lr] = a1n.w;
            s.Bs[nb][lk4+0][lr]    = b0n.x; s.Bs[nb][lk4+1][lr]    = b0n.y;
            s.Bs[nb][lk4+2][lr]    = b0n.z; s.Bs[nb][lk4+3][lr]    = b0n.w;
            s.Bs[nb][lk4+0][64+lr] = b1n.x; s.Bs[nb][lk4+1][64+lr] = b1n.y;
            s.Bs[nb][lk4+2][64+lr] = b1n.z; s.Bs[nb][lk4+3][64+lr] = b1n.w;
            __syncthreads();
        }
        buf ^= 1;
    }

    // epilogue: 16 float4 stores
    #pragma unroll
    for (int i = 0; i < 8; i++) {
        const int m = m0 + ((i < 4) ? (ty * 4 + i) : (64 + ty * 4 + i - 4));
        const int nA = n0 + tx * 4;
        const int nB = n0 + 64 + tx * 4;
        float4 r0 = make_float4(acc[i][0], acc[i][1], acc[i][2], acc[i][3]);
        float4 r1 = make_float4(acc[i][4], acc[i][5], acc[i][6], acc[i][7]);
        if (bias) {
            r0.x += bias[nA+0]; r0.y += bias[nA+1]; r0.z += bias[nA+2]; r0.w += bias[nA+3];
            r1.x += bias[nB+0]; r1.y += bias[nB+1]; r1.z += bias[nB+2]; r1.w += bias[nB+3];
        }
        *(float4*)&C[(size_t)m * ldc + nA] = r0;
        *(float4*)&C[(size_t)m * ldc + nB] = r1;
    }
}

// ---------------------------------------------------------------------------
// Projection GEMM: C[M,N] = A[M,K] @ W[N,K]^T (+bias). grid (N/128, M/128).
// ---------------------------------------------------------------------------
__global__ void __launch_bounds__(256, 2)
proj_kernel(const float* __restrict__ A,
            const float* __restrict__ W,
            float* __restrict__ C,
            const float* __restrict__ bias,
            int N, int K)
{
    __shared__ Smem128 s;
    gemm128_body(A, K, W, K, C, N, K, bias, blockIdx.y * 128, blockIdx.x * 128, s);
}

// ---------------------------------------------------------------------------
// scores[b,h] = q_bh @ k_bh^T.  grid (SEQ/128, SEQ/128, BH).
// ---------------------------------------------------------------------------
__global__ void __launch_bounds__(256, 2)
scores_kernel()
{
    __shared__ Smem128 s;
    const int bh = blockIdx.z;
    const int b  = bh >> 4;
    const int h  = bh & 15;
    const float* A = g_q + (size_t)b * SEQ * DMODEL + h * DHEAD;
    const float* B = g_k + (size_t)b * SEQ * DMODEL + h * DHEAD;
    float*       C = g_sc + (size_t)bh * SEQ * SEQ;
    gemm128_body(A, DMODEL, B, DMODEL, C, SEQ, DHEAD, nullptr,
                 blockIdx.y * 128, blockIdx.x * 128, s);
}

// ---------------------------------------------------------------------------
// Row softmax over SEQ=2048 columns. One 256-thread block per row, float4 I/O.
// ---------------------------------------------------------------------------
__global__ void __launch_bounds__(256)
softmax_kernel()
{
    __shared__ float red[8];
    const int tid  = threadIdx.x;
    const int lane = tid & 31;
    const int warp = tid >> 5;
    float4* p4 = reinterpret_cast<float4*>(g_sc + (size_t)blockIdx.x * SEQ);

    float4 x0 = p4[tid];
    float4 x1 = p4[tid + 256];

    float mx = fmaxf(fmaxf(fmaxf(x0.x, x0.y), fmaxf(x0.z, x0.w)),
                     fmaxf(fmaxf(x1.x, x1.y), fmaxf(x1.z, x1.w)));
    #pragma unroll
    for (int o = 16; o > 0; o >>= 1)
        mx = fmaxf(mx, __shfl_xor_sync(0xffffffffu, mx, o));
    if (lane == 0) red[warp] = mx;
    __syncthreads();
    if (warp == 0) {
        float m = red[lane & 7];
        #pragma unroll
        for (int o = 4; o > 0; o >>= 1)
            m = fmaxf(m, __shfl_xor_sync(0xffffffffu, m, o));
        if (lane == 0) red[0] = m;
    }
    __syncthreads();
    mx = red[0];
    __syncthreads();

    x0.x = __expf(x0.x - mx); x0.y = __expf(x0.y - mx);
    x0.z = __expf(x0.z - mx); x0.w = __expf(x0.w - mx);
    x1.x = __expf(x1.x - mx); x1.y = __expf(x1.y - mx);
    x1.z = __expf(x1.z - mx); x1.w = __expf(x1.w - mx);
    float sum = x0.x + x0.y + x0.z + x0.w + x1.x + x1.y + x1.z + x1.w;
    #pragma unroll
    for (int o = 16; o > 0; o >>= 1)
        sum += __shfl_xor_sync(0xffffffffu, sum, o);
    if (lane == 0) red[warp] = sum;
    __syncthreads();
    if (warp == 0) {
        float sm = red[lane & 7];
        #pragma unroll
        for (int o = 4; o > 0; o >>= 1)
            sm += __shfl_xor_sync(0xffffffffu, sm, o);
        if (lane == 0) red[0] = sm;
    }
    __syncthreads();
    const float inv = 1.0f / red[0];

    x0.x *= inv; x0.y *= inv; x0.z *= inv; x0.w *= inv;
    x1.x *= inv; x1.y *= inv; x1.z *= inv; x1.w *= inv;
    p4[tid]       = x0;
    p4[tid + 256] = x1;
}

// ---------------------------------------------------------------------------
// attn_bh (SEQ x 64) = P_bh (SEQ x SEQ) @ v_bh (SEQ x 64). NN GEMM.
// Tile 128x64, 256 threads, 8x4 microtile, double-buffered.
// grid (1, SEQ/128, BH).
// ---------------------------------------------------------------------------
__global__ void __launch_bounds__(256, 2)
pv_kernel()
{
    __shared__ float As[2][KT][132];
    __shared__ float Bs[2][KT][68];

    const int bh = blockIdx.z;
    const int b  = bh >> 4;
    const int h  = bh & 15;
    const float* A = g_sc   + (size_t)bh * SEQ * SEQ;                 // lda = SEQ
    const float* B = g_v    + (size_t)b * SEQ * DMODEL + h * DHEAD;   // ldb = DMODEL
    float*       C = g_attn + (size_t)b * SEQ * DMODEL + h * DHEAD;   // ldc = DMODEL

    const int tid = threadIdx.x;
    const int tx  = tid & 15;          // cols tx*4 .. tx*4+3
    const int ty  = tid >> 4;          // rows ty*4, 64+ty*4
    const int lr  = tid >> 2;          // A-load row 0..63
    const int lk4 = (tid & 3) * 4;     // A-load k 0,4,8,12
    const int bk  = tid >> 4;          // B-load k 0..15
    const int bn  = (tid & 15) * 4;    // B-load col

    const int m0 = blockIdx.y * 128;

    float acc[8][4] = {};

    // prologue
    {
        float4 a0 = *(const float4*)&A[(size_t)(m0 + lr)      * SEQ + lk4];
        float4 a1 = *(const float4*)&A[(size_t)(m0 + 64 + lr) * SEQ + lk4];
        float4 bv = *(const float4*)&B[(size_t)bk * DMODEL + bn];
        As[0][lk4+0][lr]    = a0.x; As[0][lk4+1][lr]    = a0.y;
        As[0][lk4+2][lr]    = a0.z; As[0][lk4+3][lr]    = a0.w;
        As[0][lk4+0][64+lr] = a1.x; As[0][lk4+1][64+lr] = a1.y;
        As[0][lk4+2][64+lr] = a1.z; As[0][lk4+3][64+lr] = a1.w;
        *(float4*)&Bs[0][bk][bn] = bv;
    }
    __syncthreads();

    int buf = 0;
    for (int k0 = KT; k0 <= SEQ; k0 += KT) {
        const bool has_next = (k0 < SEQ);
        float4 a0n, a1n, bvn;
        if (has_next) {
            a0n = *(const float4*)&A[(size_t)(m0 + lr)      * SEQ + k0 + lk4];
            a1n = *(const float4*)&A[(size_t)(m0 + 64 + lr) * SEQ + k0 + lk4];
            bvn = *(const float4*)&B[(size_t)(k0 + bk) * DMODEL + bn];
        }

        #pragma unroll
        for (int kk = 0; kk < KT; kk++) {
            float4 av0 = *(const float4*)&As[buf][kk][ty * 4];
            float4 av1 = *(const float4*)&As[buf][kk][64 + ty * 4];
            float4 bv  = *(const float4*)&Bs[buf][kk][tx * 4];
            const float a[8] = {av0.x, av0.y, av0.z, av0.w, av1.x, av1.y, av1.z, av1.w};
            const float bb[4] = {bv.x, bv.y, bv.z, bv.w};
            #pragma unroll
            for (int i = 0; i < 8; i++)
                #pragma unroll
                for (int j = 0; j < 4; j++)
                    acc[i][j] = fmaf(a[i], bb[j], acc[i][j]);
        }

        if (has_next) {
            const int nb = buf ^ 1;
            As[nb][lk4+0][lr]    = a0n.x; As[nb][lk4+1][lr]    = a0n.y;
            As[nb][lk4+2][lr]    = a0n.z; As[nb][lk4+3][lr]    = a0n.w;
            As[nb][lk4+0][64+lr] = a1n.x; As[nb][lk4+1][64+lr] = a1n.y;
            As[nb][lk4+2][64+lr] = a1n.z; As[nb][lk4+3][64+lr] = a1n.w;
            *(float4*)&Bs[nb][bk][bn] = bvn;
            __syncthreads();
        }
        buf ^= 1;
    }

    #pragma unroll
    for (int i = 0; i < 8; i++) {
        const int m = m0 + ((i < 4) ? (ty * 4 + i) : (64 + ty * 4 + i - 4));
        *(float4*)&C[(size_t)m * DMODEL + tx * 4] =
            make_float4(acc[i][0], acc[i][1], acc[i][2], acc[i][3]);
    }
}

// ---------------------------------------------------------------------------
extern "C" void kernel_launch(void* const* d_in, const int* in_sizes, int n_in,
                              void* d_out, int out_size)
{
    const float* x  = (const float*)d_in[0];
    // d_in[1] = attn_weights (unused by reference forward)
    const float* Wq = (const float*)d_in[2];
    const float* Wk = (const float*)d_in[3];
    const float* Wv = (const float*)d_in[4];
    const float* Wp = (const float*)d_in[5];
    const float* bp = (const float*)d_in[6];
    float* out = (float*)d_out;

    float *q, *k, *v, *attn;
    cudaGetSymbolAddress((void**)&q,    g_q);
    cudaGetSymbolAddress((void**)&k,    g_k);
    cudaGetSymbolAddress((void**)&v,    g_v);
    cudaGetSymbolAddress((void**)&attn, g_attn);

    const dim3 blk(256);
    const dim3 grid_proj(DMODEL / 128, MROWS / 128);   // (8, 32)

    // QKV projections
    proj_kernel<<<grid_proj, blk>>>(x, Wq, q, nullptr, DMODEL, DMODEL);
    proj_kernel<<<grid_proj, blk>>>(x, Wk, k, nullptr, DMODEL, DMODEL);
    proj_kernel<<<grid_proj, blk>>>(x, Wv, v, nullptr, DMODEL, DMODEL);

    // Attention
    scores_kernel <<<dim3(SEQ / 128, SEQ / 128, BH), blk>>>();
    softmax_kernel<<<BH * SEQ, blk>>>();
    pv_kernel     <<<dim3(1, SEQ / 128, BH), blk>>>();

    // Output projection (+bias)
    proj_kernel<<<grid_proj, blk>>>(attn, Wp, out, bp, DMODEL, DMODEL);
}